// round 4
// baseline (speedup 1.0000x reference)
#include <cuda_runtime.h>
#include <stdint.h>

#define BATCH   64
#define SEQ     512
#define EMBD    768
#define DM      32
#define NH      4
#define DH      8
#define NCQ     16
#define NCODES  8192
#define NSAMP   16
#define NROWS   (BATCH * NCQ)      /* 1024 */
#define NTOK    (BATCH * SEQ)      /* 32768 */

/* ------------------------------------------------------------------ */
/* scratch (static device memory; no allocations anywhere)            */
/* ------------------------------------------------------------------ */
__device__ float g_x[NTOK * DM];
__device__ float g_qkv[NTOK * 3 * DM];
__device__ float g_ao[NTOK * DM];
__device__ float g_xc[NROWS * EMBD];
__device__ float g_xn2[NROWS];
__device__ float g_cn2[NCODES];
__device__ float g_logit[(size_t)NROWS * NCODES];
__device__ int   g_cand[(size_t)NROWS * 64];
__device__ int   g_candcnt[NROWS];
__device__ float g_thr[NROWS];
__device__ int   g_draw[NSAMP * NROWS];

/* ------------------------------------------------------------------ */
/* helpers                                                             */
/* ------------------------------------------------------------------ */
__device__ __forceinline__ float wsum(float v) {
#pragma unroll
    for (int o = 16; o; o >>= 1) v += __shfl_xor_sync(0xffffffffu, v, o);
    return v;
}
__device__ __forceinline__ float wmax(float v) {
#pragma unroll
    for (int o = 16; o; o >>= 1) v = fmaxf(v, __shfl_xor_sync(0xffffffffu, v, o));
    return v;
}

/* jax threefry2x32 with key (0, 42) */
__device__ __forceinline__ void threefry_0_42(uint32_t c0, uint32_t c1,
                                              uint32_t& o0, uint32_t& o1) {
    const uint32_t k0 = 0u, k1 = 42u, k2 = 0x1BD11BDAu ^ k0 ^ k1;
    uint32_t x0 = c0 + k0, x1 = c1 + k1;
#define TF_RND(r) { x0 += x1; x1 = __funnelshift_l(x1, x1, r); x1 ^= x0; }
    TF_RND(13) TF_RND(15) TF_RND(26) TF_RND(6)
    x0 += k1; x1 += k2 + 1u;
    TF_RND(17) TF_RND(29) TF_RND(16) TF_RND(24)
    x0 += k2; x1 += k0 + 2u;
    TF_RND(13) TF_RND(15) TF_RND(26) TF_RND(6)
    x0 += k0; x1 += k1 + 3u;
    TF_RND(17) TF_RND(29) TF_RND(16) TF_RND(24)
    x0 += k1; x1 += k2 + 4u;
    TF_RND(13) TF_RND(15) TF_RND(26) TF_RND(6)
    x0 += k2; x1 += k0 + 5u;
#undef TF_RND
    o0 = x0; o1 = x1;
}

/* jax gumbel from raw uint32: u = max(tiny, bits->[0,1)); g = -log(-log(u)) */
__device__ __forceinline__ float gumbel_bits(uint32_t bits) {
    float f = __uint_as_float((bits >> 9) | 0x3f800000u) - 1.0f;
    float u = fmaxf(f, 1.17549435e-38f);
    return -logf(-logf(u));
}

/* partitionable threefry random bits for flat index i (< 2^32):
   bits[i] = o0 ^ o1 of threefry(key, (hi=0, lo=i))                    */
__device__ __forceinline__ float gumbel_idx(uint32_t i) {
    uint32_t o0, o1;
    threefry_0_42(0u, i, o0, o1);
    return gumbel_bits(o0 ^ o1);
}

/* ------------------------------------------------------------------ */
/* 1. x = xcq @ fc_in_w^T + b       (warp per token)                   */
/* ------------------------------------------------------------------ */
__global__ void __launch_bounds__(256) k_fc_in(const float* __restrict__ xcq,
                        const float* __restrict__ W,
                        const float* __restrict__ b) {
    __shared__ float sx[8][EMBD];
    int warp = threadIdx.x >> 5, lane = threadIdx.x & 31;
    int t = blockIdx.x * 8 + warp;
    const float* xr = xcq + (size_t)t * EMBD;
    for (int i = lane; i < EMBD; i += 32) sx[warp][i] = xr[i];
    __syncwarp();
    float acc = b[lane];
    const float* wr = W + lane * EMBD;
#pragma unroll 8
    for (int k = 0; k < EMBD; k++) acc += sx[warp][k] * wr[k];
    g_x[t * DM + lane] = acc;
}

/* ------------------------------------------------------------------ */
/* 2. qkv = x @ Win^T + b  (warp per token, 3 outs per lane)           */
/* ------------------------------------------------------------------ */
__global__ void __launch_bounds__(256) k_qkv(const float* __restrict__ W,
                                             const float* __restrict__ b) {
    int warp = threadIdx.x >> 5, lane = threadIdx.x & 31;
    int t = blockIdx.x * 8 + warp;
    float xv = g_x[t * DM + lane];
    float a0 = 0.f, a1 = 0.f, a2 = 0.f;
#pragma unroll
    for (int c = 0; c < 32; c++) {
        float x = __shfl_sync(0xffffffffu, xv, c);
        a0 += x * W[lane * DM + c];
        a1 += x * W[(lane + 32) * DM + c];
        a2 += x * W[(lane + 64) * DM + c];
    }
    float* o = g_qkv + (size_t)t * 96;
    o[lane]      = a0 + b[lane];
    o[lane + 32] = a1 + b[lane + 32];
    o[lane + 64] = a2 + b[lane + 64];
}

/* ------------------------------------------------------------------ */
/* 3. attention: block per (batch, head); K/V staged in smem           */
/* ------------------------------------------------------------------ */
__global__ void __launch_bounds__(256) k_attn(const int* __restrict__ amask) {
    __shared__ float Ks[512 * 9];
    __shared__ float Vs[512 * 9];
    __shared__ float vm[512];
    int b = blockIdx.x >> 2, h = blockIdx.x & 3;
    for (int i = threadIdx.x; i < 512 * 8; i += 256) {
        int key = i >> 3, d = i & 7;
        const float* base = g_qkv + ((size_t)(b * 512 + key)) * 96;
        Ks[key * 9 + d] = base[32 + h * 8 + d];
        Vs[key * 9 + d] = base[64 + h * 8 + d];
    }
    for (int key = threadIdx.x; key < 512; key += 256)
        vm[key] = (key < NCQ || amask[b * (SEQ - NCQ) + key - NCQ] != 0) ? 1.f : 0.f;
    __syncthreads();

    int warp = threadIdx.x >> 5, lane = threadIdx.x & 31;
    for (int q = warp; q < 512; q += 8) {
        float qv[8];
        const float* qb = g_qkv + ((size_t)(b * 512 + q)) * 96 + h * 8;
#pragma unroll
        for (int d = 0; d < 8; d++) qv[d] = qb[d];
        float sc[16];
#pragma unroll
        for (int j = 0; j < 16; j++) {
            int key = j * 32 + lane;
            const float* kr = Ks + key * 9;
            float dot = 0.f;
#pragma unroll
            for (int d = 0; d < 8; d++) dot += qv[d] * kr[d];
            sc[j] = (vm[key] != 0.f) ? dot * 0.35355339059327373f : -1e9f;
        }
        float m = sc[0];
#pragma unroll
        for (int j = 1; j < 16; j++) m = fmaxf(m, sc[j]);
        m = wmax(m);
        float s = 0.f;
#pragma unroll
        for (int j = 0; j < 16; j++) { sc[j] = expf(sc[j] - m); s += sc[j]; }
        s = wsum(s);
#pragma unroll
        for (int d = 0; d < 8; d++) {
            float pv = 0.f;
#pragma unroll
            for (int j = 0; j < 16; j++) pv += sc[j] * Vs[(j * 32 + lane) * 9 + d];
            pv = wsum(pv);
            if (lane == 0)
                g_ao[(size_t)(b * 512 + q) * DM + h * 8 + d] = pv / s;
        }
    }
}

/* ------------------------------------------------------------------ */
/* 4. x = LN1(x + o @ Wout^T + bo)  (warp per token)                   */
/* ------------------------------------------------------------------ */
__global__ void __launch_bounds__(256) k_projln(const float* __restrict__ Wo,
                         const float* __restrict__ bo,
                         const float* __restrict__ lg, const float* __restrict__ lb) {
    int warp = threadIdx.x >> 5, lane = threadIdx.x & 31;
    int t = blockIdx.x * 8 + warp;
    float ov = g_ao[t * DM + lane];
    float acc = bo[lane];
#pragma unroll
    for (int c = 0; c < 32; c++)
        acc += __shfl_sync(0xffffffffu, ov, c) * Wo[lane * DM + c];
    float r = g_x[t * DM + lane] + acc;
    float mu = wsum(r) * (1.f / 32.f);
    float d = r - mu;
    float var = wsum(d * d) * (1.f / 32.f);
    g_x[t * DM + lane] = lg[lane] * d / sqrtf(var + 1e-5f) + lb[lane];
}

/* ------------------------------------------------------------------ */
/* 5. x = LN2(x + relu(x@W1^T+b1)@W2^T+b2)  (warp per token)           */
/* ------------------------------------------------------------------ */
__global__ void __launch_bounds__(256) k_ffln(const float* __restrict__ W1,
                       const float* __restrict__ b1,
                       const float* __restrict__ W2, const float* __restrict__ b2,
                       const float* __restrict__ lg, const float* __restrict__ lb) {
    int warp = threadIdx.x >> 5, lane = threadIdx.x & 31;
    int t = blockIdx.x * 8 + warp;
    float xv = g_x[t * DM + lane];
    float h0 = b1[lane], h1 = b1[lane + 32];
#pragma unroll
    for (int c = 0; c < 32; c++) {
        float x = __shfl_sync(0xffffffffu, xv, c);
        h0 += x * W1[lane * DM + c];
        h1 += x * W1[(lane + 32) * DM + c];
    }
    h0 = fmaxf(h0, 0.f); h1 = fmaxf(h1, 0.f);
    float acc = b2[lane];
#pragma unroll
    for (int c = 0; c < 32; c++) {
        acc += __shfl_sync(0xffffffffu, h0, c) * W2[lane * 64 + c];
        acc += __shfl_sync(0xffffffffu, h1, c) * W2[lane * 64 + 32 + c];
    }
    float r = xv + acc;
    float mu = wsum(r) * (1.f / 32.f);
    float d = r - mu;
    float var = wsum(d * d) * (1.f / 32.f);
    g_x[t * DM + lane] = lg[lane] * d / sqrtf(var + 1e-5f) + lb[lane];
}

/* ------------------------------------------------------------------ */
/* 6. xc_out = x[:, :16] @ fc_out_w^T + b  ; plus |row|^2              */
/* ------------------------------------------------------------------ */
__global__ void __launch_bounds__(256) k_fcout(const float* __restrict__ W,
                                               const float* __restrict__ b) {
    __shared__ float xs[DM];
    __shared__ float red[256];
    int n = blockIdx.x;
    int t = (n >> 4) * SEQ + (n & 15);
    if (threadIdx.x < DM) xs[threadIdx.x] = g_x[t * DM + threadIdx.x];
    __syncthreads();
    float sq = 0.f;
#pragma unroll
    for (int r = 0; r < 3; r++) {
        int j = threadIdx.x + 256 * r;
        float acc = b[j];
#pragma unroll
        for (int c = 0; c < 32; c++) acc += xs[c] * W[j * DM + c];
        g_xc[(size_t)n * EMBD + j] = acc;
        sq += acc * acc;
    }
    red[threadIdx.x] = sq;
    __syncthreads();
    for (int o = 128; o; o >>= 1) {
        if (threadIdx.x < o) red[threadIdx.x] += red[threadIdx.x + o];
        __syncthreads();
    }
    if (threadIdx.x == 0) g_xn2[n] = red[0];
}

/* ------------------------------------------------------------------ */
/* 7. codebook row norms                                               */
/* ------------------------------------------------------------------ */
__global__ void __launch_bounds__(256) k_cn2(const float* __restrict__ cb) {
    int warp = threadIdx.x >> 5, lane = threadIdx.x & 31;
    int c = blockIdx.x * 8 + warp;
    const float* r = cb + (size_t)c * EMBD;
    float s = 0.f;
    for (int i = lane; i < EMBD; i += 32) { float v = r[i]; s += v * v; }
    s = wsum(s);
    if (lane == 0) g_cn2[c] = s;
}

/* ------------------------------------------------------------------ */
/* 8. logits = -(|x|^2 + |c|^2 - 2 x.c) - 1e-5   (fp32 tiled GEMM)     */
/* ------------------------------------------------------------------ */
__global__ void __launch_bounds__(256) k_gemm(const float* __restrict__ cb) {
    __shared__ float As[16][65];
    __shared__ float Bs[16][65];
    int bn = blockIdx.x * 64, bm = blockIdx.y * 64;
    int tx = threadIdx.x & 15, ty = threadIdx.x >> 4;
    float acc[4][4] = {};
    for (int k0 = 0; k0 < EMBD; k0 += 16) {
        for (int i = threadIdx.x; i < 1024; i += 256) {
            int m = i >> 4, kk = i & 15;
            As[kk][m] = g_xc[(size_t)(bm + m) * EMBD + k0 + kk];
            Bs[kk][m] = cb[(size_t)(bn + m) * EMBD + k0 + kk];
        }
        __syncthreads();
#pragma unroll
        for (int kk = 0; kk < 16; kk++) {
            float a[4], bv[4];
#pragma unroll
            for (int i = 0; i < 4; i++) a[i] = As[kk][ty * 4 + i];
#pragma unroll
            for (int j = 0; j < 4; j++) bv[j] = Bs[kk][tx * 4 + j];
#pragma unroll
            for (int i = 0; i < 4; i++)
#pragma unroll
                for (int j = 0; j < 4; j++) acc[i][j] += a[i] * bv[j];
        }
        __syncthreads();
    }
#pragma unroll
    for (int i = 0; i < 4; i++) {
        int m = bm + ty * 4 + i;
        float xn = g_xn2[m];
#pragma unroll
        for (int j = 0; j < 4; j++) {
            int c = bn + tx * 4 + j;
            g_logit[(size_t)m * NCODES + c] =
                -(xn + g_cn2[c] - 2.0f * acc[i][j]) - 1e-5f;
        }
    }
}

/* ------------------------------------------------------------------ */
/* 9. fused per-row max + candidate collection (gumbel span 20.413:    */
/*    only logit >= rowmax - 20.45 can ever win the argmax)            */
/* ------------------------------------------------------------------ */
__global__ void __launch_bounds__(256) k_cand() {
    __shared__ float red[256];
    __shared__ float s_thr;
    __shared__ int   s_cnt;
    int n = blockIdx.x;
    const float* row = g_logit + (size_t)n * NCODES;
    float m = -3.0e38f;
    for (int k = threadIdx.x; k < NCODES; k += 256) m = fmaxf(m, row[k]);
    red[threadIdx.x] = m;
    __syncthreads();
    for (int o = 128; o; o >>= 1) {
        if (threadIdx.x < o) red[threadIdx.x] = fmaxf(red[threadIdx.x], red[threadIdx.x + o]);
        __syncthreads();
    }
    if (threadIdx.x == 0) { s_thr = red[0] - 20.45f; s_cnt = 0; }
    __syncthreads();
    float thr = s_thr;
    for (int k = threadIdx.x; k < NCODES; k += 256) {
        if (row[k] >= thr) {
            int p = atomicAdd(&s_cnt, 1);
            if (p < 64) g_cand[(size_t)n * 64 + p] = k;
        }
    }
    __syncthreads();
    if (threadIdx.x == 0) { g_candcnt[n] = s_cnt; g_thr[n] = thr; }
}

/* ------------------------------------------------------------------ */
/* 10. exact jax categorical (partitionable threefry):                 */
/*     bits[i] = o0^o1 of threefry((0,42),(0,i)), i = s*2^23+n*2^13+k  */
/*     one warp per sample s; overflow rows fall back to full scan     */
/* ------------------------------------------------------------------ */
__global__ void __launch_bounds__(512) k_sample() {
    int n = blockIdx.x;
    int s = threadIdx.x >> 5, lane = threadIdx.x & 31;   /* s = 0..15 */
    int cnt = g_candcnt[n];
    const float* row = g_logit + (size_t)n * NCODES;
    uint32_t base = ((uint32_t)s << 23) | ((uint32_t)n << 13);
    float v = -3.0e38f;
    int best = 0x7fffffff;
    if (cnt <= 64) {
        const int* cl = g_cand + (size_t)n * 64;
        for (int ci = lane; ci < cnt; ci += 32) {
            int k = cl[ci];
            float val = row[k] + gumbel_idx(base | (uint32_t)k);
            if (val > v || (val == v && k < best)) { v = val; best = k; }
        }
    } else {
        float thr = g_thr[n];
        for (int k = lane; k < NCODES; k += 32) {
            float lg = row[k];
            if (lg >= thr) {
                float val = lg + gumbel_idx(base | (uint32_t)k);
                if (val > v || (val == v && k < best)) { v = val; best = k; }
            }
        }
    }
#pragma unroll
    for (int o = 16; o; o >>= 1) {
        float tv = __shfl_down_sync(0xffffffffu, v, o);
        int   tk = __shfl_down_sync(0xffffffffu, best, o);
        if (tv > v || (tv == v && tk < best)) { v = tv; best = tk; }
    }
    if (lane == 0) g_draw[s * NROWS + n] = best;
}

/* ------------------------------------------------------------------ */
/* 11. output: xc_out + (mean(cb[draws]) - xc_out)                     */
/* ------------------------------------------------------------------ */
__global__ void __launch_bounds__(256) k_out(const float* __restrict__ cb,
                                             float* __restrict__ out) {
    __shared__ int dr[16];
    int n = blockIdx.x;
    if (threadIdx.x < 16) dr[threadIdx.x] = g_draw[threadIdx.x * NROWS + n];
    __syncthreads();
#pragma unroll
    for (int r = 0; r < 3; r++) {
        int j = threadIdx.x + 256 * r;
        float q = 0.f;
#pragma unroll
        for (int s = 0; s < 16; s++) q += cb[(size_t)dr[s] * EMBD + j];
        float xc = g_xc[(size_t)n * EMBD + j];
        out[(size_t)n * EMBD + j] = xc + (q * 0.0625f - xc);
    }
}

/* ------------------------------------------------------------------ */
extern "C" void kernel_launch(void* const* d_in, const int* in_sizes, int n_in,
                              void* d_out, int out_size) {
    const float* xcq      = (const float*)d_in[0];
    const int*   amask    = (const int*)  d_in[1];
    const float* fc_in_w  = (const float*)d_in[2];
    const float* fc_in_b  = (const float*)d_in[3];
    const float* fc_out_w = (const float*)d_in[4];
    const float* fc_out_b = (const float*)d_in[5];
    const float* enc_in_w = (const float*)d_in[6];
    const float* enc_in_b = (const float*)d_in[7];
    const float* enc_ow   = (const float*)d_in[8];
    const float* enc_ob   = (const float*)d_in[9];
    const float* ff1_w    = (const float*)d_in[10];
    const float* ff1_b    = (const float*)d_in[11];
    const float* ff2_w    = (const float*)d_in[12];
    const float* ff2_b    = (const float*)d_in[13];
    const float* ln1_g    = (const float*)d_in[14];
    const float* ln1_b    = (const float*)d_in[15];
    const float* ln2_g    = (const float*)d_in[16];
    const float* ln2_b    = (const float*)d_in[17];
    const float* cb       = (const float*)d_in[18];
    float* out = (float*)d_out;

    k_fc_in<<<NTOK / 8, 256>>>(xcq, fc_in_w, fc_in_b);
    for (int l = 0; l < 2; l++) {
        k_qkv<<<NTOK / 8, 256>>>(enc_in_w + l * 96 * DM, enc_in_b + l * 96);
        k_attn<<<BATCH * NH, 256>>>(amask);
        k_projln<<<NTOK / 8, 256>>>(enc_ow + l * DM * DM, enc_ob + l * DM,
                                    ln1_g + l * DM, ln1_b + l * DM);
        k_ffln<<<NTOK / 8, 256>>>(ff1_w + l * 64 * DM, ff1_b + l * 64,
                                  ff2_w + l * DM * 64, ff2_b + l * DM,
                                  ln2_g + l * DM, ln2_b + l * DM);
    }
    k_fcout<<<NROWS, 256>>>(fc_out_w, fc_out_b);
    k_cn2<<<NCODES / 8, 256>>>(cb);
    k_gemm<<<dim3(NCODES / 64, NROWS / 64), 256>>>(cb);
    k_cand<<<NROWS, 256>>>();
    k_sample<<<NROWS, 512>>>();
    k_out<<<NROWS, 256>>>(cb, out);

    /* second tuple element: passthrough copy of xcq */
    cudaMemcpyAsync(out + (size_t)NROWS * EMBD, xcq,
                    (size_t)NTOK * EMBD * sizeof(float),
                    cudaMemcpyDeviceToDevice);
}

// round 5
// speedup vs baseline: 6.1647x; 6.1647x over previous
#include <cuda_runtime.h>
#include <stdint.h>

#define BATCH   64
#define SEQ     512
#define EMBD    768
#define DM      32
#define NH      4
#define NCQ     16
#define NCODES  8192
#define NSAMP   16
#define NROWS   (BATCH * NCQ)      /* 1024 */
#define NTOK    (BATCH * SEQ)      /* 32768 */

/* ------------------------------------------------------------------ */
/* scratch (static device memory; no allocations anywhere)            */
/* ------------------------------------------------------------------ */
__device__ float g_x[NTOK * DM];
__device__ float g_qkv[NTOK * 96];
__device__ float g_ao[NTOK * DM];
__device__ float g_xc[NROWS * EMBD];
__device__ float g_xn2[NROWS];
__device__ float g_cn2[NCODES];
__device__ float g_logit[(size_t)NROWS * NCODES];
__device__ int   g_cand[(size_t)NROWS * 64];
__device__ int   g_candcnt[NROWS];
__device__ float g_thr[NROWS];
__device__ int   g_draw[NSAMP * NROWS];

/* transposed weights: Wt[k][out] for broadcast-friendly access */
__device__ float gWt_fcin[768 * 32];
__device__ float gWt_qkv[2 * 32 * 96];
__device__ float gWt_out[2 * 32 * 32];
__device__ float gWt_ff1[2 * 32 * 64];
__device__ float gWt_ff2[2 * 64 * 32];

/* ------------------------------------------------------------------ */
/* PRNG: jax threefry2x32, key (0,42), partitionable scheme            */
/* ------------------------------------------------------------------ */
__device__ __forceinline__ void threefry_0_42(uint32_t c0, uint32_t c1,
                                              uint32_t& o0, uint32_t& o1) {
    const uint32_t k0 = 0u, k1 = 42u, k2 = 0x1BD11BDAu ^ k0 ^ k1;
    uint32_t x0 = c0 + k0, x1 = c1 + k1;
#define TF_RND(r) { x0 += x1; x1 = __funnelshift_l(x1, x1, r); x1 ^= x0; }
    TF_RND(13) TF_RND(15) TF_RND(26) TF_RND(6)
    x0 += k1; x1 += k2 + 1u;
    TF_RND(17) TF_RND(29) TF_RND(16) TF_RND(24)
    x0 += k2; x1 += k0 + 2u;
    TF_RND(13) TF_RND(15) TF_RND(26) TF_RND(6)
    x0 += k0; x1 += k1 + 3u;
    TF_RND(17) TF_RND(29) TF_RND(16) TF_RND(24)
    x0 += k1; x1 += k2 + 4u;
    TF_RND(13) TF_RND(15) TF_RND(26) TF_RND(6)
    x0 += k2; x1 += k0 + 5u;
#undef TF_RND
    o0 = x0; o1 = x1;
}
__device__ __forceinline__ float gumbel_idx(uint32_t i) {
    uint32_t o0, o1;
    threefry_0_42(0u, i, o0, o1);
    uint32_t bits = o0 ^ o1;
    float f = __uint_as_float((bits >> 9) | 0x3f800000u) - 1.0f;
    float u = fmaxf(f, 1.17549435e-38f);
    return -logf(-logf(u));
}

/* ------------------------------------------------------------------ */
/* 0. weight transposes (tiny, once per launch)                        */
/* ------------------------------------------------------------------ */
__global__ void __launch_bounds__(256) k_prep(
        const float* __restrict__ fcinw, const float* __restrict__ encinw,
        const float* __restrict__ encow, const float* __restrict__ ff1w,
        const float* __restrict__ ff2w) {
    int i = blockIdx.x * 256 + threadIdx.x;
    if (i < 24576) { int k = i >> 5, c = i & 31; gWt_fcin[i] = fcinw[c * 768 + k]; return; }
    int j = i - 24576;
    if (j < 6144) { int l = j / 3072, r = j % 3072; int k = r / 96, q = r % 96;
        gWt_qkv[j] = encinw[l * 3072 + q * 32 + k]; return; }
    j -= 6144;
    if (j < 2048) { int l = j / 1024, r = j % 1024; int k = r >> 5, c = r & 31;
        gWt_out[j] = encow[l * 1024 + c * 32 + k]; return; }
    j -= 2048;
    if (j < 4096) { int l = j / 2048, r = j % 2048; int k = r / 64, c = r % 64;
        gWt_ff1[j] = ff1w[l * 2048 + c * 32 + k]; return; }
    j -= 4096;
    if (j < 4096) { int l = j / 2048, r = j % 2048; int k = r >> 5, c = r & 31;
        gWt_ff2[j] = ff2w[l * 2048 + c * 64 + k]; }
}

/* ------------------------------------------------------------------ */
/* 1. x = xcq @ fc_in_w^T + b  (thread per token, chunked smem)        */
/* ------------------------------------------------------------------ */
__global__ void __launch_bounds__(128) k_fcin(const float* __restrict__ xcq,
                                              const float* __restrict__ bias) {
    __shared__ float sx[128 * 33];
    __shared__ float sw[32 * 32];
    int tok0 = blockIdx.x * 128;
    int t = threadIdx.x;
    float acc[32];
#pragma unroll
    for (int c = 0; c < 32; c++) acc[c] = 0.f;
    for (int k0 = 0; k0 < 768; k0 += 32) {
        for (int i = t; i < 4096; i += 128) {
            int tok = i >> 5, k = i & 31;
            sx[tok * 33 + k] = xcq[(size_t)(tok0 + tok) * 768 + k0 + k];
        }
        for (int i = t; i < 1024; i += 128) sw[i] = gWt_fcin[k0 * 32 + i];
        __syncthreads();
#pragma unroll 4
        for (int k = 0; k < 32; k++) {
            float xk = sx[t * 33 + k];
            const float4* w4 = (const float4*)(sw + k * 32);
#pragma unroll
            for (int c4 = 0; c4 < 8; c4++) {
                float4 w = w4[c4];
                acc[c4 * 4 + 0] += xk * w.x;
                acc[c4 * 4 + 1] += xk * w.y;
                acc[c4 * 4 + 2] += xk * w.z;
                acc[c4 * 4 + 3] += xk * w.w;
            }
        }
        __syncthreads();
    }
    float4* xo = (float4*)(g_x + (size_t)(tok0 + t) * 32);
#pragma unroll
    for (int c4 = 0; c4 < 8; c4++)
        xo[c4] = make_float4(acc[c4 * 4 + 0] + bias[c4 * 4 + 0],
                             acc[c4 * 4 + 1] + bias[c4 * 4 + 1],
                             acc[c4 * 4 + 2] + bias[c4 * 4 + 2],
                             acc[c4 * 4 + 3] + bias[c4 * 4 + 3]);
}

/* ------------------------------------------------------------------ */
/* 2. qkv = x @ Win^T + b  (thread per token, weights broadcast)       */
/* ------------------------------------------------------------------ */
__global__ void __launch_bounds__(128) k_qkvt(int layer,
                                              const float* __restrict__ encinb) {
    __shared__ float sw[32 * 96];
    __shared__ float sb[96];
    int t = threadIdx.x;
    int token = blockIdx.x * 128 + t;
    for (int i = t; i < 3072; i += 128) sw[i] = gWt_qkv[layer * 3072 + i];
    if (t < 96) sb[t] = encinb[layer * 96 + t];
    __syncthreads();
    float x[32];
    const float4* xr = (const float4*)(g_x + (size_t)token * 32);
#pragma unroll
    for (int i = 0; i < 8; i++) {
        float4 v = xr[i];
        x[i * 4] = v.x; x[i * 4 + 1] = v.y; x[i * 4 + 2] = v.z; x[i * 4 + 3] = v.w;
    }
    float* out = g_qkv + (size_t)token * 96;
#pragma unroll
    for (int part = 0; part < 3; part++) {
        float acc[32];
#pragma unroll
        for (int c = 0; c < 32; c++) acc[c] = sb[part * 32 + c];
#pragma unroll 4
        for (int k = 0; k < 32; k++) {
            float xk = x[k];
            const float4* w4 = (const float4*)(sw + k * 96 + part * 32);
#pragma unroll
            for (int c4 = 0; c4 < 8; c4++) {
                float4 w = w4[c4];
                acc[c4 * 4 + 0] += xk * w.x;
                acc[c4 * 4 + 1] += xk * w.y;
                acc[c4 * 4 + 2] += xk * w.z;
                acc[c4 * 4 + 3] += xk * w.w;
            }
        }
        float4* o4 = (float4*)(out + part * 32);
#pragma unroll
        for (int c4 = 0; c4 < 8; c4++)
            o4[c4] = make_float4(acc[c4 * 4], acc[c4 * 4 + 1], acc[c4 * 4 + 2], acc[c4 * 4 + 3]);
    }
}

/* ------------------------------------------------------------------ */
/* 3. attention: thread per query, online softmax                      */
/* ------------------------------------------------------------------ */
__global__ void __launch_bounds__(512) k_attn(const int* __restrict__ amask) {
    __shared__ float Ks[512 * 8];
    __shared__ float Vs[512 * 8];
    __shared__ float vm[512];
    int b = blockIdx.x >> 2, h = blockIdx.x & 3;
    const float* qkvb = g_qkv + (size_t)b * 512 * 96;
    for (int i = threadIdx.x; i < 4096; i += 512) {
        int key = i >> 3, d = i & 7;
        Ks[i] = qkvb[key * 96 + 32 + h * 8 + d];
        Vs[i] = qkvb[key * 96 + 64 + h * 8 + d];
    }
    {
        int key = threadIdx.x;
        vm[key] = (key < NCQ || amask[b * (SEQ - NCQ) + key - NCQ] != 0) ? 1.f : 0.f;
    }
    __syncthreads();
    int q = threadIdx.x;
    float qv[8];
    {
        const float4* qp = (const float4*)(qkvb + q * 96 + h * 8);
        float4 q0 = qp[0], q1 = qp[1];
        qv[0] = q0.x; qv[1] = q0.y; qv[2] = q0.z; qv[3] = q0.w;
        qv[4] = q1.x; qv[5] = q1.y; qv[6] = q1.z; qv[7] = q1.w;
    }
    float m = -3.0e38f, s = 0.f;
    float pv[8];
#pragma unroll
    for (int d = 0; d < 8; d++) pv[d] = 0.f;
    const float4* K4 = (const float4*)Ks;
    const float4* V4 = (const float4*)Vs;
    for (int key = 0; key < 512; key++) {
        if (vm[key] == 0.f) continue;
        float4 ka = K4[key * 2], kb = K4[key * 2 + 1];
        float dot = qv[0] * ka.x + qv[1] * ka.y + qv[2] * ka.z + qv[3] * ka.w
                  + qv[4] * kb.x + qv[5] * kb.y + qv[6] * kb.z + qv[7] * kb.w;
        dot *= 0.35355339059327373f;
        float4 va = V4[key * 2], vb = V4[key * 2 + 1];
        if (dot <= m) {
            float e = expf(dot - m);
            s += e;
            pv[0] += e * va.x; pv[1] += e * va.y; pv[2] += e * va.z; pv[3] += e * va.w;
            pv[4] += e * vb.x; pv[5] += e * vb.y; pv[6] += e * vb.z; pv[7] += e * vb.w;
        } else {
            float r = expf(m - dot);
            s = s * r + 1.f;
            pv[0] = pv[0] * r + va.x; pv[1] = pv[1] * r + va.y;
            pv[2] = pv[2] * r + va.z; pv[3] = pv[3] * r + va.w;
            pv[4] = pv[4] * r + vb.x; pv[5] = pv[5] * r + vb.y;
            pv[6] = pv[6] * r + vb.z; pv[7] = pv[7] * r + vb.w;
            m = dot;
        }
    }
    float inv = 1.f / s;
    float4* o4 = (float4*)(g_ao + ((size_t)(b * 512 + q)) * 32 + h * 8);
    o4[0] = make_float4(pv[0] * inv, pv[1] * inv, pv[2] * inv, pv[3] * inv);
    o4[1] = make_float4(pv[4] * inv, pv[5] * inv, pv[6] * inv, pv[7] * inv);
}

/* ------------------------------------------------------------------ */
/* 4. fused: x = LN2(LN1(x + proj(ao)) + ff(...)); optional next qkv   */
/* ------------------------------------------------------------------ */
__global__ void __launch_bounds__(128) k_post(int layer, int do_qkv,
        const float* __restrict__ encob,
        const float* __restrict__ ln1g, const float* __restrict__ ln1b,
        const float* __restrict__ ff1b, const float* __restrict__ ff2b,
        const float* __restrict__ ln2g, const float* __restrict__ ln2b,
        const float* __restrict__ encinb) {
    __shared__ float sWo[1024], sW1[2048], sW2[2048], sWq[3072];
    __shared__ float sbo[32], sl1g[32], sl1b[32], sb1[64], sb2[32],
                     sl2g[32], sl2b[32], sbq[96];
    int t = threadIdx.x;
    for (int i = t; i < 1024; i += 128) sWo[i] = gWt_out[layer * 1024 + i];
    for (int i = t; i < 2048; i += 128) sW1[i] = gWt_ff1[layer * 2048 + i];
    for (int i = t; i < 2048; i += 128) sW2[i] = gWt_ff2[layer * 2048 + i];
    if (do_qkv) for (int i = t; i < 3072; i += 128) sWq[i] = gWt_qkv[layer * 3072 + 3072 + i];
    if (t < 32) {
        sbo[t] = encob[layer * 32 + t];
        sl1g[t] = ln1g[layer * 32 + t]; sl1b[t] = ln1b[layer * 32 + t];
        sb2[t] = ff2b[layer * 32 + t];
        sl2g[t] = ln2g[layer * 32 + t]; sl2b[t] = ln2b[layer * 32 + t];
    }
    if (t < 64) sb1[t] = ff1b[layer * 64 + t];
    if (do_qkv && t < 96) sbq[t] = encinb[(layer + 1) * 96 + t];
    __syncthreads();
    int token = blockIdx.x * 128 + t;

    /* proj(ao) */
    float a[32];
    {
        const float4* ar = (const float4*)(g_ao + (size_t)token * 32);
#pragma unroll
        for (int i = 0; i < 8; i++) {
            float4 v = ar[i];
            a[i * 4] = v.x; a[i * 4 + 1] = v.y; a[i * 4 + 2] = v.z; a[i * 4 + 3] = v.w;
        }
    }
    float r[32];
#pragma unroll
    for (int c = 0; c < 32; c++) r[c] = sbo[c];
#pragma unroll 4
    for (int k = 0; k < 32; k++) {
        float ak = a[k];
        const float4* w4 = (const float4*)(sWo + k * 32);
#pragma unroll
        for (int c4 = 0; c4 < 8; c4++) {
            float4 w = w4[c4];
            r[c4 * 4 + 0] += ak * w.x; r[c4 * 4 + 1] += ak * w.y;
            r[c4 * 4 + 2] += ak * w.z; r[c4 * 4 + 3] += ak * w.w;
        }
    }
    /* + x, LN1 */
    {
        const float4* xr = (const float4*)(g_x + (size_t)token * 32);
#pragma unroll
        for (int i = 0; i < 8; i++) {
            float4 v = xr[i];
            r[i * 4] += v.x; r[i * 4 + 1] += v.y; r[i * 4 + 2] += v.z; r[i * 4 + 3] += v.w;
        }
    }
    float mu = 0.f;
#pragma unroll
    for (int c = 0; c < 32; c++) mu += r[c];
    mu *= (1.f / 32.f);
    float var = 0.f;
#pragma unroll
    for (int c = 0; c < 32; c++) { float d = r[c] - mu; var += d * d; }
    var *= (1.f / 32.f);
    float isd = sqrtf(var + 1e-5f);
#pragma unroll
    for (int c = 0; c < 32; c++) r[c] = sl1g[c] * (r[c] - mu) / isd + sl1b[c];

    /* ff: out = relu(r@W1^T)@W2^T, two halves of h */
    float out[32];
#pragma unroll
    for (int c = 0; c < 32; c++) out[c] = sb2[c];
#pragma unroll
    for (int half = 0; half < 2; half++) {
        float h[32];
#pragma unroll
        for (int c = 0; c < 32; c++) h[c] = sb1[half * 32 + c];
#pragma unroll 4
        for (int k = 0; k < 32; k++) {
            float xk = r[k];
            const float4* w4 = (const float4*)(sW1 + k * 64 + half * 32);
#pragma unroll
            for (int c4 = 0; c4 < 8; c4++) {
                float4 w = w4[c4];
                h[c4 * 4 + 0] += xk * w.x; h[c4 * 4 + 1] += xk * w.y;
                h[c4 * 4 + 2] += xk * w.z; h[c4 * 4 + 3] += xk * w.w;
            }
        }
#pragma unroll
        for (int c = 0; c < 32; c++) h[c] = fmaxf(h[c], 0.f);
#pragma unroll 4
        for (int k = 0; k < 32; k++) {
            float hk = h[k];
            const float4* w4 = (const float4*)(sW2 + (half * 32 + k) * 32);
#pragma unroll
            for (int c4 = 0; c4 < 8; c4++) {
                float4 w = w4[c4];
                out[c4 * 4 + 0] += hk * w.x; out[c4 * 4 + 1] += hk * w.y;
                out[c4 * 4 + 2] += hk * w.z; out[c4 * 4 + 3] += hk * w.w;
            }
        }
    }
    /* residual + LN2 */
#pragma unroll
    for (int c = 0; c < 32; c++) r[c] += out[c];
    mu = 0.f;
#pragma unroll
    for (int c = 0; c < 32; c++) mu += r[c];
    mu *= (1.f / 32.f);
    var = 0.f;
#pragma unroll
    for (int c = 0; c < 32; c++) { float d = r[c] - mu; var += d * d; }
    var *= (1.f / 32.f);
    isd = sqrtf(var + 1e-5f);
#pragma unroll
    for (int c = 0; c < 32; c++) r[c] = sl2g[c] * (r[c] - mu) / isd + sl2b[c];

    float4* xo = (float4*)(g_x + (size_t)token * 32);
#pragma unroll
    for (int c4 = 0; c4 < 8; c4++)
        xo[c4] = make_float4(r[c4 * 4], r[c4 * 4 + 1], r[c4 * 4 + 2], r[c4 * 4 + 3]);

    if (do_qkv) {
        float* qo = g_qkv + (size_t)token * 96;
#pragma unroll
        for (int part = 0; part < 3; part++) {
            float acc[32];
#pragma unroll
            for (int c = 0; c < 32; c++) acc[c] = sbq[part * 32 + c];
#pragma unroll 4
            for (int k = 0; k < 32; k++) {
                float xk = r[k];
                const float4* w4 = (const float4*)(sWq + k * 96 + part * 32);
#pragma unroll
                for (int c4 = 0; c4 < 8; c4++) {
                    float4 w = w4[c4];
                    acc[c4 * 4 + 0] += xk * w.x; acc[c4 * 4 + 1] += xk * w.y;
                    acc[c4 * 4 + 2] += xk * w.z; acc[c4 * 4 + 3] += xk * w.w;
                }
            }
            float4* o4 = (float4*)(qo + part * 32);
#pragma unroll
            for (int c4 = 0; c4 < 8; c4++)
                o4[c4] = make_float4(acc[c4 * 4], acc[c4 * 4 + 1],
                                     acc[c4 * 4 + 2], acc[c4 * 4 + 3]);
        }
    }
}

/* ------------------------------------------------------------------ */
/* 5. xc_out = x[:, :16] @ fc_out_w^T + b ; plus |row|^2               */
/* ------------------------------------------------------------------ */
__global__ void __launch_bounds__(256) k_fcout(const float* __restrict__ W,
                                               const float* __restrict__ b) {
    __shared__ float xs[DM];
    __shared__ float red[256];
    int n = blockIdx.x;
    int t = (n >> 4) * SEQ + (n & 15);
    if (threadIdx.x < DM) xs[threadIdx.x] = g_x[t * DM + threadIdx.x];
    __syncthreads();
    float sq = 0.f;
#pragma unroll
    for (int r = 0; r < 3; r++) {
        int j = threadIdx.x + 256 * r;
        float acc = b[j];
#pragma unroll
        for (int c = 0; c < 32; c++) acc += xs[c] * W[j * DM + c];
        g_xc[(size_t)n * EMBD + j] = acc;
        sq += acc * acc;
    }
    red[threadIdx.x] = sq;
    __syncthreads();
    for (int o = 128; o; o >>= 1) {
        if (threadIdx.x < o) red[threadIdx.x] += red[threadIdx.x + o];
        __syncthreads();
    }
    if (threadIdx.x == 0) g_xn2[n] = red[0];
}

/* ------------------------------------------------------------------ */
/* 6. codebook row norms                                               */
/* ------------------------------------------------------------------ */
__global__ void __launch_bounds__(256) k_cn2(const float* __restrict__ cb) {
    int warp = threadIdx.x >> 5, lane = threadIdx.x & 31;
    int c = blockIdx.x * 8 + warp;
    const float* r = cb + (size_t)c * EMBD;
    float s = 0.f;
    for (int i = lane; i < EMBD; i += 32) { float v = r[i]; s += v * v; }
#pragma unroll
    for (int o = 16; o; o >>= 1) s += __shfl_xor_sync(0xffffffffu, s, o);
    if (lane == 0) g_cn2[c] = s;
}

/* ------------------------------------------------------------------ */
/* 7. logits GEMM: 128x128 tile, 8x8/thread, split-tile fragments      */
/* ------------------------------------------------------------------ */
__global__ void __launch_bounds__(256) k_gemm(const float* __restrict__ cb) {
    __shared__ float As[16][132];
    __shared__ float Bs[16][132];
    int bm = blockIdx.y * 128, bn = blockIdx.x * 128;
    int tid = threadIdx.x;
    int tx = tid & 15, ty = tid >> 4;
    float acc[8][8];
#pragma unroll
    for (int i = 0; i < 8; i++)
#pragma unroll
        for (int j = 0; j < 8; j++) acc[i][j] = 0.f;

    int lm = tid >> 1, lk = (tid & 1) * 8;
    for (int k0 = 0; k0 < 768; k0 += 16) {
        {
            const float4* sa = (const float4*)(g_xc + (size_t)(bm + lm) * 768 + k0 + lk);
            float4 v0 = sa[0], v1 = sa[1];
            As[lk + 0][lm] = v0.x; As[lk + 1][lm] = v0.y; As[lk + 2][lm] = v0.z; As[lk + 3][lm] = v0.w;
            As[lk + 4][lm] = v1.x; As[lk + 5][lm] = v1.y; As[lk + 6][lm] = v1.z; As[lk + 7][lm] = v1.w;
            const float4* sb = (const float4*)(cb + (size_t)(bn + lm) * 768 + k0 + lk);
            float4 w0 = sb[0], w1 = sb[1];
            Bs[lk + 0][lm] = w0.x; Bs[lk + 1][lm] = w0.y; Bs[lk + 2][lm] = w0.z; Bs[lk + 3][lm] = w0.w;
            Bs[lk + 4][lm] = w1.x; Bs[lk + 5][lm] = w1.y; Bs[lk + 6][lm] = w1.z; Bs[lk + 7][lm] = w1.w;
        }
        __syncthreads();
#pragma unroll
        for (int kk = 0; kk < 16; kk++) {
            float av[8], bv[8];
            float4 a0 = *(const float4*)&As[kk][ty * 4];
            float4 a1 = *(const float4*)&As[kk][64 + ty * 4];
            float4 b0 = *(const float4*)&Bs[kk][tx * 4];
            float4 b1 = *(const float4*)&Bs[kk][64 + tx * 4];
            av[0] = a0.x; av[1] = a0.y; av[2] = a0.z; av[3] = a0.w;
            av[4] = a1.x; av[5] = a1.y; av[6] = a1.z; av[7] = a1.w;
            bv[0] = b0.x; bv[1] = b0.y; bv[2] = b0.z; bv[3] = b0.w;
            bv[4] = b1.x; bv[5] = b1.y; bv[6] = b1.z; bv[7] = b1.w;
#pragma unroll
            for (int i = 0; i < 8; i++)
#pragma unroll
                for (int j = 0; j < 8; j++) acc[i][j] += av[i] * bv[j];
        }
        __syncthreads();
    }
    /* epilogue: logit = -(|x|^2 + |c|^2 - 2 x.c) - 1e-5 */
    int rows[8], cols[8];
#pragma unroll
    for (int i = 0; i < 4; i++) { rows[i] = bm + ty * 4 + i; rows[4 + i] = bm + 64 + ty * 4 + i; }
#pragma unroll
    for (int j = 0; j < 4; j++) { cols[j] = bn + tx * 4 + j; cols[4 + j] = bn + 64 + tx * 4 + j; }
    float cn[8];
#pragma unroll
    for (int j = 0; j < 8; j++) cn[j] = g_cn2[cols[j]];
#pragma unroll
    for (int i = 0; i < 8; i++) {
        float xn = g_xn2[rows[i]];
        float* rowp = g_logit + (size_t)rows[i] * NCODES;
        float4 s0, s1;
        s0.x = -(xn + cn[0] - 2.f * acc[i][0]) - 1e-5f;
        s0.y = -(xn + cn[1] - 2.f * acc[i][1]) - 1e-5f;
        s0.z = -(xn + cn[2] - 2.f * acc[i][2]) - 1e-5f;
        s0.w = -(xn + cn[3] - 2.f * acc[i][3]) - 1e-5f;
        s1.x = -(xn + cn[4] - 2.f * acc[i][4]) - 1e-5f;
        s1.y = -(xn + cn[5] - 2.f * acc[i][5]) - 1e-5f;
        s1.z = -(xn + cn[6] - 2.f * acc[i][6]) - 1e-5f;
        s1.w = -(xn + cn[7] - 2.f * acc[i][7]) - 1e-5f;
        *(float4*)(rowp + cols[0]) = s0;
        *(float4*)(rowp + cols[4]) = s1;
    }
}

/* ------------------------------------------------------------------ */
/* 8. fused rowmax + candidates (gumbel span 20.413)                   */
/* ------------------------------------------------------------------ */
__global__ void __launch_bounds__(256) k_cand() {
    __shared__ float red[256];
    __shared__ float s_thr;
    __shared__ int   s_cnt;
    int n = blockIdx.x;
    const float* row = g_logit + (size_t)n * NCODES;
    float m = -3.0e38f;
    for (int k = threadIdx.x; k < NCODES; k += 256) m = fmaxf(m, row[k]);
    red[threadIdx.x] = m;
    __syncthreads();
    for (int o = 128; o; o >>= 1) {
        if (threadIdx.x < o) red[threadIdx.x] = fmaxf(red[threadIdx.x], red[threadIdx.x + o]);
        __syncthreads();
    }
    if (threadIdx.x == 0) { s_thr = red[0] - 20.45f; s_cnt = 0; }
    __syncthreads();
    float thr = s_thr;
    for (int k = threadIdx.x; k < NCODES; k += 256) {
        if (row[k] >= thr) {
            int p = atomicAdd(&s_cnt, 1);
            if (p < 64) g_cand[(size_t)n * 64 + p] = k;
        }
    }
    __syncthreads();
    if (threadIdx.x == 0) { g_candcnt[n] = s_cnt; g_thr[n] = thr; }
}

/* ------------------------------------------------------------------ */
/* 9. exact jax categorical (partitionable threefry)                   */
/* ------------------------------------------------------------------ */
__global__ void __launch_bounds__(512) k_sample() {
    int n = blockIdx.x;
    int s = threadIdx.x >> 5, lane = threadIdx.x & 31;
    int cnt = g_candcnt[n];
    const float* row = g_logit + (size_t)n * NCODES;
    uint32_t base = ((uint32_t)s << 23) | ((uint32_t)n << 13);
    float v = -3.0e38f;
    int best = 0x7fffffff;
    if (cnt <= 64) {
        const int* cl = g_cand + (size_t)n * 64;
        for (int ci = lane; ci < cnt; ci += 32) {
            int k = cl[ci];
            float val = row[k] + gumbel_idx(base | (uint32_t)k);
            if (val > v || (val == v && k < best)) { v = val; best = k; }
        }
    } else {
        float thr = g_thr[n];
        for (int k = lane; k < NCODES; k += 32) {
            float lg = row[k];
            if (lg >= thr) {
                float val = lg + gumbel_idx(base | (uint32_t)k);
                if (val > v || (val == v && k < best)) { v = val; best = k; }
            }
        }
    }
#pragma unroll
    for (int o = 16; o; o >>= 1) {
        float tv = __shfl_down_sync(0xffffffffu, v, o);
        int   tk = __shfl_down_sync(0xffffffffu, best, o);
        if (tv > v || (tv == v && tk < best)) { v = tv; best = tk; }
    }
    if (lane == 0) g_draw[s * NROWS + n] = best;
}

/* ------------------------------------------------------------------ */
/* 10. output: xc_out + (mean(cb[draws]) - xc_out)                     */
/* ------------------------------------------------------------------ */
__global__ void __launch_bounds__(256) k_out(const float* __restrict__ cb,
                                             float* __restrict__ out) {
    __shared__ int dr[16];
    int n = blockIdx.x;
    if (threadIdx.x < 16) dr[threadIdx.x] = g_draw[threadIdx.x * NROWS + n];
    __syncthreads();
#pragma unroll
    for (int r = 0; r < 3; r++) {
        int j = threadIdx.x + 256 * r;
        float q = 0.f;
#pragma unroll
        for (int s = 0; s < 16; s++) q += cb[(size_t)dr[s] * EMBD + j];
        float xc = g_xc[(size_t)n * EMBD + j];
        out[(size_t)n * EMBD + j] = xc + (q * 0.0625f - xc);
    }
}

/* ------------------------------------------------------------------ */
extern "C" void kernel_launch(void* const* d_in, const int* in_sizes, int n_in,
                              void* d_out, int out_size) {
    const float* xcq      = (const float*)d_in[0];
    const int*   amask    = (const int*)  d_in[1];
    const float* fc_in_w  = (const float*)d_in[2];
    const float* fc_in_b  = (const float*)d_in[3];
    const float* fc_out_w = (const float*)d_in[4];
    const float* fc_out_b = (const float*)d_in[5];
    const float* enc_in_w = (const float*)d_in[6];
    const float* enc_in_b = (const float*)d_in[7];
    const float* enc_ow   = (const float*)d_in[8];
    const float* enc_ob   = (const float*)d_in[9];
    const float* ff1_w    = (const float*)d_in[10];
    const float* ff1_b    = (const float*)d_in[11];
    const float* ff2_w    = (const float*)d_in[12];
    const float* ff2_b    = (const float*)d_in[13];
    const float* ln1_g    = (const float*)d_in[14];
    const float* ln1_b    = (const float*)d_in[15];
    const float* ln2_g    = (const float*)d_in[16];
    const float* ln2_b    = (const float*)d_in[17];
    const float* cb       = (const float*)d_in[18];
    float* out = (float*)d_out;

    k_prep<<<160, 256>>>(fc_in_w, enc_in_w, enc_ow, ff1_w, ff2_w);
    k_cn2<<<NCODES / 8, 256>>>(cb);
    k_fcin<<<NTOK / 128, 128>>>(xcq, fc_in_b);
    k_qkvt<<<NTOK / 128, 128>>>(0, enc_in_b);
    k_attn<<<BATCH * NH, 512>>>(amask);
    k_post<<<NTOK / 128, 128>>>(0, 1, enc_ob, ln1_g, ln1_b, ff1_b, ff2_b,
                                ln2_g, ln2_b, enc_in_b);
    k_attn<<<BATCH * NH, 512>>>(amask);
    k_post<<<NTOK / 128, 128>>>(1, 0, enc_ob, ln1_g, ln1_b, ff1_b, ff2_b,
                                ln2_g, ln2_b, enc_in_b);
    k_fcout<<<NROWS, 256>>>(fc_out_w, fc_out_b);
    k_gemm<<<dim3(NCODES / 128, NROWS / 128), 256>>>(cb);
    k_cand<<<NROWS, 256>>>();
    k_sample<<<NROWS, 512>>>();
    k_out<<<NROWS, 256>>>(cb, out);

    /* second tuple element: passthrough copy of xcq */
    cudaMemcpyAsync(out + (size_t)NROWS * EMBD, xcq,
                    (size_t)NTOK * EMBD * sizeof(float),
                    cudaMemcpyDeviceToDevice);
}